// round 11
// baseline (speedup 1.0000x reference)
#include <cuda_runtime.h>
#include <cuda_fp16.h>
#include <cstdint>

// out = (idx[...,0] >= 0) ? shaded[idx0] : (1,1,1)
// (binary-weight alpha composite keeps only the first fragment; bg_mask on
//  slot 0 overrides the rest — only idx[...,0] matters)
//
// Single fused kernel: first n_chunks CTAs shade the point table into gmem
// and publish per-chunk flags; all CTAs issue their idx loads, wait for the
// flags, then gather + TMA-store. Shading is re-executed on every call
// (flags only enforce first-call ordering; replays rewrite identical bytes).

#define MAX_P 131072
#define THREADS 128
#define PX_PER_THREAD 4
#define TILE_PX (THREADS * PX_PER_THREAD)     // 512 px per CTA
#define TILE_OUT_FLOATS (TILE_PX * 3)         // 1536 floats = 6 KB
#define MAX_CHUNKS 128

// fp16 rgb packed into 8B: .x = half2(r,g), .y = half2(b,_)
__device__ uint2 g_tab[MAX_P];
__device__ int   g_flag[MAX_CHUNKS];          // zero-initialized .bss

__global__ __launch_bounds__(THREADS) void fused_kernel(
        const int*   __restrict__ idx,
        const float* __restrict__ features,
        const float* __restrict__ normals,
        const float* __restrict__ light_dir,
        float* __restrict__ out,
        int n_pix, int K, int P, int n_chunks, int chunk_sz) {
    __shared__ __align__(16) float s_out[TILE_OUT_FLOATS];

    int tid  = threadIdx.x;
    int lane = tid & 31;
    int warp = tid >> 5;
    int bid  = blockIdx.x;

    // ---- Phase 0: shading prologue (first n_chunks CTAs only) ----
    if (bid < n_chunks) {
        float lx = light_dir[0], ly = light_dir[1], lz = light_dir[2];
        float inv = rsqrtf(lx * lx + ly * ly + lz * lz);
        lx *= inv; ly *= inv; lz *= inv;

        int lo = bid * chunk_sz;
        int hi = lo + chunk_sz; if (hi > P) hi = P;
        for (int i = lo + tid; i < hi; i += THREADS) {
            float nx = normals[3 * i + 0];
            float ny = normals[3 * i + 1];
            float nz = normals[3 * i + 2];
            float ndl = fabsf(nx * lx + ny * ly + nz * lz);
            float s = 0.6f + 0.8f * ndl;  // AMBIENT + DIFFUSE * |n.l|

            float r = fminf(fmaxf(features[3 * i + 0] * s, 0.0f), 1.0f);
            float g = fminf(fmaxf(features[3 * i + 1] * s, 0.0f), 1.0f);
            float b = fminf(fmaxf(features[3 * i + 2] * s, 0.0f), 1.0f);

            __half2 rg = __floats2half2_rn(r, g);
            __half2 b0 = __floats2half2_rn(b, 0.0f);
            uint2 packed;
            packed.x = *(unsigned int*)&rg;
            packed.y = *(unsigned int*)&b0;
            g_tab[i] = packed;
        }
        __threadfence();          // each thread orders its table stores
        __syncthreads();          // all threads' fences done
        if (tid == 0) {
            asm volatile("st.release.gpu.global.s32 [%0], %1;"
                         :: "l"(&g_flag[bid]), "r"(1) : "memory");
        }
    }

    // ---- Phase 1: issue this CTA's idx loads (overlaps the table wait) ----
    long tile_base = (long)bid * TILE_PX;
    bool full = (tile_base + TILE_PX) <= (long)n_pix;
    int  lbase = warp * (32 * PX_PER_THREAD) + lane;   // local px of j=0
    long base  = tile_base + lbase;

    int ids[PX_PER_THREAD];
#pragma unroll
    for (int j = 0; j < PX_PER_THREAD; j++) {
        long p = base + 32 * j;
        ids[j] = (full || p < n_pix) ? __ldcs(&idx[p * (long)K]) : -1;
    }

    // ---- Phase 2: wait until the whole table is published ----
    if (tid == 0) {
        volatile int* vf = g_flag;
        while (true) {
            int ok = 1;
            for (int c = 0; c < n_chunks; c++) ok &= (vf[c] != 0);
            if (ok) break;
            __nanosleep(256);
        }
    }
    __syncthreads();
    __threadfence();  // acquire: table reads below see published data

    // ---- Phase 3: gather + composite (identical to proven R10 path) ----
    const uint2* __restrict__ tab = g_tab;
    const unsigned int ONE2 = 0x3C003C00u;  // half2(1,1)
    const unsigned int ONE0 = 0x00003C00u;  // half2(1,0)

    uint2 v[PX_PER_THREAD];
#pragma unroll
    for (int j = 0; j < PX_PER_THREAD; j++) {
        v[j] = (ids[j] >= 0) ? __ldg(&tab[ids[j]]) : make_uint2(ONE2, ONE0);
    }

    if (full) {
#pragma unroll
        for (int j = 0; j < PX_PER_THREAD; j++) {
            int l = lbase + 32 * j;
            float2 rg = __half22float2(*(__half2*)&v[j].x);
            float2 b0 = __half22float2(*(__half2*)&v[j].y);
            s_out[l * 3 + 0] = rg.x;   // stride-3 words: conflict-free
            s_out[l * 3 + 1] = rg.y;
            s_out[l * 3 + 2] = b0.x;
        }
        __syncthreads();

        if (tid == 0) {
            float* gdst = out + tile_base * 3;
            uint32_t saddr;
            asm("{ .reg .u64 t; cvta.to.shared.u64 t, %1; cvt.u32.u64 %0, t; }"
                : "=r"(saddr) : "l"(s_out));
            asm volatile("fence.proxy.async.shared::cta;" ::: "memory");
            asm volatile(
                "cp.async.bulk.global.shared::cta.bulk_group [%0], [%1], %2;"
                :: "l"(gdst), "r"(saddr), "n"(TILE_OUT_FLOATS * 4)
                : "memory");
            asm volatile("cp.async.bulk.commit_group;" ::: "memory");
            asm volatile("cp.async.bulk.wait_group 0;" ::: "memory");
        }
    } else {
        // partial tail tile: plain scalar stores
#pragma unroll
        for (int j = 0; j < PX_PER_THREAD; j++) {
            long p = base + 32 * j;
            if (p < n_pix) {
                float2 rg = __half22float2(*(__half2*)&v[j].x);
                float2 b0 = __half22float2(*(__half2*)&v[j].y);
                out[p * 3 + 0] = rg.x;
                out[p * 3 + 1] = rg.y;
                out[p * 3 + 2] = b0.x;
            }
        }
    }
}

extern "C" void kernel_launch(void* const* d_in, const int* in_sizes, int n_in,
                              void* d_out, int out_size) {
    const int*   idx       = (const int*)d_in[0];
    const float* features  = (const float*)d_in[1];
    const float* normals   = (const float*)d_in[2];
    const float* light_dir = (const float*)d_in[3];

    int n_pix = out_size / 3;                 // N*H*W
    int K     = in_sizes[0] / n_pix;          // fragments per pixel (10)
    int P     = in_sizes[1] / 3;              // number of points (100000)
    if (P > MAX_P) P = MAX_P;

    int blocks = (int)(((long)n_pix + TILE_PX - 1) / TILE_PX);

    // shade chunks: at most MAX_CHUNKS, always fewer than wave-1 capacity
    int chunk_sz = (P + MAX_CHUNKS - 1) / MAX_CHUNKS;
    if (chunk_sz < 1024) chunk_sz = 1024;
    int n_chunks = (P + chunk_sz - 1) / chunk_sz;
    if (n_chunks > blocks) n_chunks = blocks;  // safety for tiny grids

    fused_kernel<<<blocks, THREADS>>>(idx, features, normals, light_dir,
                                      (float*)d_out, n_pix, K, P,
                                      n_chunks, chunk_sz);
}

// round 12
// speedup vs baseline: 5.8238x; 5.8238x over previous
#include <cuda_runtime.h>
#include <cuda_fp16.h>
#include <cstdint>

// out = (idx[...,0] >= 0) ? shaded[idx0] : (1,1,1)
// (binary-weight alpha composite keeps only the first fragment; bg_mask on
//  slot 0 overrides the rest — only idx[...,0] matters)
//
// Two kernels + PDL: composite launches programmatically-dependent on shade,
// front-runs its idx loads, then griddepcontrol.wait before gathering from
// the shaded table. Hardware-ordered — no flag polling (R11's mistake).

#define MAX_P 131072
#define THREADS 128
#define PX_PER_THREAD 4
#define TILE_PX (THREADS * PX_PER_THREAD)     // 512 px per CTA
#define TILE_OUT_FLOATS (TILE_PX * 3)         // 1536 floats = 6 KB

// fp16 rgb packed into 8B: .x = half2(r,g), .y = half2(b,_)
__device__ uint2 g_tab[MAX_P];

__global__ void shade_kernel(const float* __restrict__ features,
                             const float* __restrict__ normals,
                             const float* __restrict__ light_dir,
                             int P) {
    int i = blockIdx.x * blockDim.x + threadIdx.x;
    if (i < P) {
        float lx = light_dir[0], ly = light_dir[1], lz = light_dir[2];
        float inv = rsqrtf(lx * lx + ly * ly + lz * lz);
        lx *= inv; ly *= inv; lz *= inv;

        float nx = normals[3 * i + 0];
        float ny = normals[3 * i + 1];
        float nz = normals[3 * i + 2];
        float ndl = fabsf(nx * lx + ny * ly + nz * lz);
        float s = 0.6f + 0.8f * ndl;  // AMBIENT + DIFFUSE * |n.l|

        float r = fminf(fmaxf(features[3 * i + 0] * s, 0.0f), 1.0f);
        float g = fminf(fmaxf(features[3 * i + 1] * s, 0.0f), 1.0f);
        float b = fminf(fmaxf(features[3 * i + 2] * s, 0.0f), 1.0f);

        __half2 rg = __floats2half2_rn(r, g);
        __half2 b0 = __floats2half2_rn(b, 0.0f);
        uint2 packed;
        packed.x = *(unsigned int*)&rg;
        packed.y = *(unsigned int*)&b0;
        g_tab[i] = packed;
    }
    // allow the dependent composite grid to begin launching
    asm volatile("griddepcontrol.launch_dependents;" ::: "memory");
}

// R10 composite + PDL wait between the idx-load phase and the table gathers.
__global__ __launch_bounds__(THREADS) void composite_kernel(
        const int* __restrict__ idx,
        float* __restrict__ out,
        int n_pix, int K) {
    __shared__ __align__(16) float s_out[TILE_OUT_FLOATS];

    const uint2* __restrict__ tab = g_tab;
    int tid  = threadIdx.x;
    int lane = tid & 31;
    int warp = tid >> 5;

    long tile_base = (long)blockIdx.x * TILE_PX;
    bool full = (tile_base + TILE_PX) <= (long)n_pix;
    int  lbase = warp * (32 * PX_PER_THREAD) + lane;   // local px of j=0
    long base  = tile_base + lbase;

    // Phase 1: idx loads — independent of the shade table, run before wait
    int ids[PX_PER_THREAD];
#pragma unroll
    for (int j = 0; j < PX_PER_THREAD; j++) {
        long p = base + 32 * j;
        ids[j] = (full || p < n_pix) ? __ldcs(&idx[p * (long)K]) : -1;
    }

    // Phase 2: wait for the shade grid's memory to be visible
    asm volatile("griddepcontrol.wait;" ::: "memory");

    // white in packed-fp16 form: half2(1,1), half2(1,0)
    const unsigned int ONE2 = 0x3C003C00u;
    const unsigned int ONE0 = 0x00003C00u;

    uint2 v[PX_PER_THREAD];
#pragma unroll
    for (int j = 0; j < PX_PER_THREAD; j++) {
        v[j] = (ids[j] >= 0) ? __ldg(&tab[ids[j]]) : make_uint2(ONE2, ONE0);
    }

    if (full) {
#pragma unroll
        for (int j = 0; j < PX_PER_THREAD; j++) {
            int l = lbase + 32 * j;
            float2 rg = __half22float2(*(__half2*)&v[j].x);
            float2 b0 = __half22float2(*(__half2*)&v[j].y);
            s_out[l * 3 + 0] = rg.x;   // stride-3 words: conflict-free
            s_out[l * 3 + 1] = rg.y;
            s_out[l * 3 + 2] = b0.x;
        }
        __syncthreads();

        if (tid == 0) {
            float* gdst = out + tile_base * 3;
            uint32_t saddr;
            asm("{ .reg .u64 t; cvta.to.shared.u64 t, %1; cvt.u32.u64 %0, t; }"
                : "=r"(saddr) : "l"(s_out));
            asm volatile("fence.proxy.async.shared::cta;" ::: "memory");
            asm volatile(
                "cp.async.bulk.global.shared::cta.bulk_group [%0], [%1], %2;"
                :: "l"(gdst), "r"(saddr), "n"(TILE_OUT_FLOATS * 4)
                : "memory");
            asm volatile("cp.async.bulk.commit_group;" ::: "memory");
            asm volatile("cp.async.bulk.wait_group 0;" ::: "memory");
        }
    } else {
        // partial tail tile: plain scalar stores
#pragma unroll
        for (int j = 0; j < PX_PER_THREAD; j++) {
            long p = base + 32 * j;
            if (p < n_pix) {
                float2 rg = __half22float2(*(__half2*)&v[j].x);
                float2 b0 = __half22float2(*(__half2*)&v[j].y);
                out[p * 3 + 0] = rg.x;
                out[p * 3 + 1] = rg.y;
                out[p * 3 + 2] = b0.x;
            }
        }
    }
}

extern "C" void kernel_launch(void* const* d_in, const int* in_sizes, int n_in,
                              void* d_out, int out_size) {
    const int*   idx       = (const int*)d_in[0];
    const float* features  = (const float*)d_in[1];
    const float* normals   = (const float*)d_in[2];
    const float* light_dir = (const float*)d_in[3];

    int n_pix = out_size / 3;                 // N*H*W
    int K     = in_sizes[0] / n_pix;          // fragments per pixel (10)
    int P     = in_sizes[1] / 3;              // number of points (100000)
    if (P > MAX_P) P = MAX_P;

    // shade (primary)
    {
        int threads = 256;
        int blocks = (P + threads - 1) / threads;
        shade_kernel<<<blocks, threads>>>(features, normals, light_dir, P);
    }

    // composite (secondary, programmatic dependent launch)
    {
        int blocks = (int)(((long)n_pix + TILE_PX - 1) / TILE_PX);

        cudaLaunchConfig_t cfg = {};
        cfg.gridDim  = dim3((unsigned)blocks, 1, 1);
        cfg.blockDim = dim3(THREADS, 1, 1);
        cfg.dynamicSmemBytes = 0;
        cfg.stream = 0;

        cudaLaunchAttribute attrs[1];
        attrs[0].id = cudaLaunchAttributeProgrammaticStreamSerialization;
        attrs[0].val.programmaticStreamSerializationAllowed = 1;
        cfg.attrs = attrs;
        cfg.numAttrs = 1;

        cudaError_t err = cudaLaunchKernelEx(&cfg, composite_kernel,
                                             idx, (float*)d_out, n_pix, K);
        if (err != cudaSuccess) {
            // fallback: plain serialized launch (still correct)
            composite_kernel<<<blocks, THREADS>>>(idx, (float*)d_out,
                                                  n_pix, K);
        }
    }
}

// round 13
// speedup vs baseline: 5.9221x; 1.0169x over previous
#include <cuda_runtime.h>
#include <cuda_fp16.h>
#include <cstdint>

// out = (idx[...,0] >= 0) ? shaded[idx0] : (1,1,1)
// (binary-weight alpha composite keeps only the first fragment; bg_mask on
//  slot 0 overrides the rest — only idx[...,0] matters)
//
// shade + PDL-dependent persistent composite (single wave, 2368 CTAs,
// grid-stride over 512-px tiles; per tile: idx LDGs -> gathers -> smem ->
// one cp.async.bulk store).

#define MAX_P 131072
#define THREADS 128
#define PX_PER_THREAD 4
#define TILE_PX (THREADS * PX_PER_THREAD)     // 512 px per tile
#define TILE_OUT_FLOATS (TILE_PX * 3)         // 1536 floats = 6 KB
#define PERSIST_CTAS 2368                     // 148 SMs * 16 CTAs (128thr, <=32regs)

// fp16 rgb packed into 8B: .x = half2(r,g), .y = half2(b,_)
__device__ uint2 g_tab[MAX_P];

__global__ void shade_kernel(const float* __restrict__ features,
                             const float* __restrict__ normals,
                             const float* __restrict__ light_dir,
                             int P) {
    int i = blockIdx.x * blockDim.x + threadIdx.x;
    if (i < P) {
        float lx = light_dir[0], ly = light_dir[1], lz = light_dir[2];
        float inv = rsqrtf(lx * lx + ly * ly + lz * lz);
        lx *= inv; ly *= inv; lz *= inv;

        float nx = normals[3 * i + 0];
        float ny = normals[3 * i + 1];
        float nz = normals[3 * i + 2];
        float ndl = fabsf(nx * lx + ny * ly + nz * lz);
        float s = 0.6f + 0.8f * ndl;  // AMBIENT + DIFFUSE * |n.l|

        float r = fminf(fmaxf(features[3 * i + 0] * s, 0.0f), 1.0f);
        float g = fminf(fmaxf(features[3 * i + 1] * s, 0.0f), 1.0f);
        float b = fminf(fmaxf(features[3 * i + 2] * s, 0.0f), 1.0f);

        __half2 rg = __floats2half2_rn(r, g);
        __half2 b0 = __floats2half2_rn(b, 0.0f);
        uint2 packed;
        packed.x = *(unsigned int*)&rg;
        packed.y = *(unsigned int*)&b0;
        g_tab[i] = packed;
    }
    asm volatile("griddepcontrol.launch_dependents;" ::: "memory");
}

__global__ void __launch_bounds__(THREADS, 16) composite_kernel(
        const int* __restrict__ idx,
        float* __restrict__ out,
        int n_pix, int K, int n_tiles) {
    __shared__ __align__(16) float s_out[TILE_OUT_FLOATS];

    const uint2* __restrict__ tab = g_tab;
    int tid  = threadIdx.x;
    int lane = tid & 31;
    int warp = tid >> 5;
    int lbase = warp * (32 * PX_PER_THREAD) + lane;   // local px of j=0

    // white in packed-fp16 form: half2(1,1), half2(1,0)
    const unsigned int ONE2 = 0x3C003C00u;
    const unsigned int ONE0 = 0x00003C00u;

    uint32_t saddr;
    asm("{ .reg .u64 t; cvta.to.shared.u64 t, %1; cvt.u32.u64 %0, t; }"
        : "=r"(saddr) : "l"(s_out));

    bool issued = false;

    for (int t = blockIdx.x; t < n_tiles; t += gridDim.x) {
        long tile_base = (long)t * TILE_PX;
        bool full = (tile_base + TILE_PX) <= (long)n_pix;
        long base = tile_base + lbase;

        // Phase 1: idx loads (independent of the shaded table)
        int ids[PX_PER_THREAD];
#pragma unroll
        for (int j = 0; j < PX_PER_THREAD; j++) {
            long p = base + 32 * j;
            ids[j] = (full || p < n_pix) ? __ldcs(&idx[p * (long)K]) : -1;
        }

        // Phase 2: table must be published (no-op after first release)
        asm volatile("griddepcontrol.wait;" ::: "memory");

        // Phase 3: gathers
        uint2 v[PX_PER_THREAD];
#pragma unroll
        for (int j = 0; j < PX_PER_THREAD; j++) {
            v[j] = (ids[j] >= 0) ? __ldg(&tab[ids[j]])
                                 : make_uint2(ONE2, ONE0);
        }

        if (full) {
            // recycle smem: previous tile's bulk store must have been read out
            if (issued) {
                if (tid == 0)
                    asm volatile("cp.async.bulk.wait_group 0;" ::: "memory");
                __syncthreads();
            }
#pragma unroll
            for (int j = 0; j < PX_PER_THREAD; j++) {
                int l = lbase + 32 * j;
                float2 rg = __half22float2(*(__half2*)&v[j].x);
                float2 b0 = __half22float2(*(__half2*)&v[j].y);
                s_out[l * 3 + 0] = rg.x;   // stride-3 words: conflict-free
                s_out[l * 3 + 1] = rg.y;
                s_out[l * 3 + 2] = b0.x;
            }
            __syncthreads();

            if (tid == 0) {
                float* gdst = out + tile_base * 3;
                asm volatile("fence.proxy.async.shared::cta;" ::: "memory");
                asm volatile(
                    "cp.async.bulk.global.shared::cta.bulk_group [%0], [%1], %2;"
                    :: "l"(gdst), "r"(saddr), "n"(TILE_OUT_FLOATS * 4)
                    : "memory");
                asm volatile("cp.async.bulk.commit_group;" ::: "memory");
            }
            issued = true;
        } else {
            // partial tail tile: plain scalar stores
#pragma unroll
            for (int j = 0; j < PX_PER_THREAD; j++) {
                long p = base + 32 * j;
                if (p < n_pix) {
                    float2 rg = __half22float2(*(__half2*)&v[j].x);
                    float2 b0 = __half22float2(*(__half2*)&v[j].y);
                    out[p * 3 + 0] = rg.x;
                    out[p * 3 + 1] = rg.y;
                    out[p * 3 + 2] = b0.x;
                }
            }
        }
    }

    if (issued && tid == 0)
        asm volatile("cp.async.bulk.wait_group 0;" ::: "memory");
}

extern "C" void kernel_launch(void* const* d_in, const int* in_sizes, int n_in,
                              void* d_out, int out_size) {
    const int*   idx       = (const int*)d_in[0];
    const float* features  = (const float*)d_in[1];
    const float* normals   = (const float*)d_in[2];
    const float* light_dir = (const float*)d_in[3];

    int n_pix = out_size / 3;                 // N*H*W
    int K     = in_sizes[0] / n_pix;          // fragments per pixel (10)
    int P     = in_sizes[1] / 3;              // number of points (100000)
    if (P > MAX_P) P = MAX_P;

    // shade (primary)
    {
        int threads = 256;
        int blocks = (P + threads - 1) / threads;
        shade_kernel<<<blocks, threads>>>(features, normals, light_dir, P);
    }

    // composite (secondary, PDL; persistent single-wave grid)
    {
        int n_tiles = (int)(((long)n_pix + TILE_PX - 1) / TILE_PX);
        int blocks = n_tiles < PERSIST_CTAS ? n_tiles : PERSIST_CTAS;

        cudaLaunchConfig_t cfg = {};
        cfg.gridDim  = dim3((unsigned)blocks, 1, 1);
        cfg.blockDim = dim3(THREADS, 1, 1);
        cfg.dynamicSmemBytes = 0;
        cfg.stream = 0;

        cudaLaunchAttribute attrs[1];
        attrs[0].id = cudaLaunchAttributeProgrammaticStreamSerialization;
        attrs[0].val.programmaticStreamSerializationAllowed = 1;
        cfg.attrs = attrs;
        cfg.numAttrs = 1;

        cudaError_t err = cudaLaunchKernelEx(&cfg, composite_kernel,
                                             idx, (float*)d_out,
                                             n_pix, K, n_tiles);
        if (err != cudaSuccess) {
            composite_kernel<<<blocks, THREADS>>>(idx, (float*)d_out,
                                                  n_pix, K, n_tiles);
        }
    }
}